// round 5
// baseline (speedup 1.0000x reference)
#include <cuda_runtime.h>
#include <math.h>

// Problem constants (fixed by dataset)
#define TT 1600
#define NN 32
#define CC 512
#define SS 200
#define LL 401
#define RINGR 32                 // row ring slots (power of 2)
#define KST 6                    // trellis steps per barrier period
#define HALO 6                   // halo lanes = KST
#define SPW 52                   // states per warp = 64 - 2*KST
#define THREADS 256              // 8 warps, 2 states per thread
#define NPER 267                 // ceil((TT-1)/KST): 266*6=1596, +3 tail
#define SH_A 416                 // padded alpha array length (max state 415)
#define LOG2E 1.4426950408889634f
#define LN2   0.6931471805599453f
#define NEG2  (-1.0e30f * 1.4426950408889634f)

// dynamic smem: rowbuf[RINGR][CC] (64KB) + shA[2][SH_A]
#define SMEM_BYTES (RINGR * CC * 4 + 2 * SH_A * 4)

__device__ float g_per_ex[NN];
__device__ unsigned int g_count;

__device__ __forceinline__ float ex2f(float x) {
    float y; asm("ex2.approx.ftz.f32 %0, %1;" : "=f"(y) : "f"(x)); return y;
}
__device__ __forceinline__ float lg2f(float x) {
    float y; asm("lg2.approx.ftz.f32 %0, %1;" : "=f"(y) : "f"(x)); return y;
}
__device__ __forceinline__ void cp_async8(void* smem_dst, const void* gmem_src) {
    unsigned s = (unsigned)__cvta_generic_to_shared(smem_dst);
    asm volatile("cp.async.ca.shared.global [%0], [%1], 8;" :: "r"(s), "l"(gmem_src));
}
__device__ __forceinline__ void cp_commit() { asm volatile("cp.async.commit_group;"); }
template<int N>
__device__ __forceinline__ void cp_wait() { asm volatile("cp.async.wait_group %0;" :: "n"(N)); }

__global__ void __launch_bounds__(THREADS, 1)
ctc_kernel(const float* __restrict__ lp,       // (T, N, C)
           const int*   __restrict__ targets,  // (N, S)
           const int*   __restrict__ input_lens,
           const int*   __restrict__ target_lens,
           float*       __restrict__ out)
{
    extern __shared__ float smem[];
    float* rowbuf = smem;                    // [RINGR][CC]
    float* shA[2] = { smem + RINGR * CC, smem + RINGR * CC + SH_A };

    const int n    = blockIdx.x;
    const int tid  = threadIdx.x;
    const int w    = tid >> 5;
    const int lane = tid & 31;

    // thread owns state pair (sB, sB+1); lanes 0..5 are halo (go stale over 6 steps)
    const int  sB    = SPW * w + 2 * (lane - HALO);
    const bool owner = (lane >= HALO);

    const size_t NC = (size_t)NN * CC;
    const float* __restrict__ base = lp + (size_t)n * CC;
    const int tl = target_lens[n];
    const int il = input_lens[n];

    // ---- per-pair invariants: odd state's label + skip permission ----
    int  myExt = 0;
    bool allow = false;
    if (sB >= 0 && sB < 400) {                    // odd state sB+1 <= 399 valid
        const int idx = sB >> 1;                  // (sB+1)>>1
        myExt = targets[n * SS + idx];
        if (sB >= 2) allow = (myExt != targets[n * SS + idx - 1]);
    }

    // ---- alpha_0 (log2 domain): state 0 = row0[blank], state 1 = row0[l1] ----
    float aE = NEG2, aO = NEG2;
    if (sB == 0) {
        aE = base[0] * LOG2E;
        if (tl >= 1) aO = base[myExt] * LOG2E;
    }
    // publish initial alphas into buffer 1 (period 0 reads (0&1)^1 = 1)
    if (owner) *(float2*)(shA[1] + sB) = make_float2(aE, aO);

    // ---- cp.async prologue: rows for periods 0..2 (rows 1..18) ----
#pragma unroll
    for (int q = 0; q < 3; ++q) {
#pragma unroll
        for (int k = 1; k <= KST; ++k) {
            const int r = KST * q + k;
            cp_async8(&rowbuf[(r & (RINGR - 1)) * CC + 2 * tid],
                      base + (size_t)r * NC + 2 * tid);
        }
        cp_commit();
    }

    // ---- main loop: 6 trellis steps per barrier period ----
    for (int p = 0; p < NPER; ++p) {
        cp_wait<2>();               // this period's 6 rows landed
        __syncthreads();            // rows + previous period's shA visible

        // halo refresh (reads buffer written last period)
        if (!owner && sB >= 0) {
            const float2 v = *(const float2*)(shA[(p & 1) ^ 1] + sB);
            aE = v.x; aO = v.y;
        }

        const int t0 = KST * p;
        // issue all emit gathers up front (latency overlaps the chain)
        float eB[KST], eO[KST];
#pragma unroll
        for (int k = 0; k < KST; ++k) {
            const float* row = rowbuf + (size_t)((t0 + 1 + k) & (RINGR - 1)) * CC;
            eB[k] = row[0]     * LOG2E;   // blank emit: block-uniform broadcast LDS
            eO[k] = row[myExt] * LOG2E;   // odd-state emit: gather
        }

#pragma unroll
        for (int k = 0; k < KST; ++k) {
            const int t = t0 + 1 + k;
            const float nbO = __shfl_up_sync(0xffffffffu, aO, 1);  // alpha(sB-1)
            // even state (blank): 2-term LSE over {aE, nbO}
            const float mE = fmaxf(aE, nbO);
            const float dE = fminf(aE, nbO) - mE;
            const float nvE = mE + lg2f(1.0f + ex2f(dE)) + eB[k];
            // odd state: 3-term LSE over {aO, aE, allow ? nbO : NEG}
            const float a2  = allow ? nbO : NEG2;
            const float hi  = fmaxf(aO, aE);
            const float lo  = fminf(aO, aE);
            const float m   = fmaxf(hi, a2);
            const float mid = fminf(hi, a2);
            const float nvO = m + lg2f(1.0f + ex2f(lo - m) + ex2f(mid - m)) + eO[k];
            const bool act = (t < il);            // also covers t >= TT tail
            aE = act ? nvE : aE;
            aO = act ? nvO : aO;
        }

        // prefetch rows for period p+3 (max slot distance 24 < 32: no aliasing)
        {
            const int r0 = KST * (p + 3);
#pragma unroll
            for (int k = 1; k <= KST; ++k) {
                const int r = r0 + k;
                if (r < TT)
                    cp_async8(&rowbuf[(r & (RINGR - 1)) * CC + 2 * tid],
                              base + (size_t)r * NC + 2 * tid);
            }
            cp_commit();   // empty groups keep accounting aligned
        }

        // publish this period's alpha for next period's halo
        if (owner) *(float2*)(shA[p & 1] + sB) = make_float2(aE, aO);
    }

    // ---- final publish + readout + fused mean reduction ----
    if (owner) *(float2*)(shA[0] + sB) = make_float2(aE, aO);
    __syncthreads();

    if (tid == 0) {
        const float* a = shA[0];
        const int i_last = 2 * tl;
        const float al  = a[i_last];
        const float apv = (tl > 0) ? a[i_last - 1] : NEG2;
        const float mm  = fmaxf(al, apv);
        const float lo  = fminf(al, apv);
        float loss = -LN2 * (mm + lg2f(1.0f + ex2f(lo - mm)));
        if (!(loss < 1e29f)) loss = 0.0f;                 // zero_infinity (+NaN kill)
        const float norm = sqrtf(fmaxf((float)tl, 1.0f)); // ALPHA = 0.5
        ((volatile float*)g_per_ex)[n] = loss / norm;
        __threadfence();
        const unsigned int old = atomicAdd(&g_count, 1u);
        if ((old % NN) == (NN - 1)) {                     // last CTA of this replay reduces
            __threadfence();
            float acc = 0.0f;
#pragma unroll
            for (int i = 0; i < NN; ++i) acc += ((volatile float*)g_per_ex)[i];
            out[0] = acc / (float)NN;
        }
    }
}

extern "C" void kernel_launch(void* const* d_in, const int* in_sizes, int n_in,
                              void* d_out, int out_size)
{
    const float* log_probs   = (const float*)d_in[0];
    const int*   targets     = (const int*)d_in[1];
    const int*   input_lens  = (const int*)d_in[2];
    const int*   target_lens = (const int*)d_in[3];
    float* out = (float*)d_out;

    cudaFuncSetAttribute(ctc_kernel,
                         cudaFuncAttributeMaxDynamicSharedMemorySize, SMEM_BYTES);
    ctc_kernel<<<NN, THREADS, SMEM_BYTES>>>(log_probs, targets,
                                            input_lens, target_lens, out);
}

// round 7
// speedup vs baseline: 1.3506x; 1.3506x over previous
#include <cuda_runtime.h>
#include <math.h>

// Problem constants (fixed by dataset)
#define TT 1600
#define NN 32
#define CC 512
#define SS 200
#define RINGR 32               // row ring slots per example (power of 2)
#define KST 6                  // trellis steps per barrier period
#define HALO 6                 // halo lanes per warp
#define SPW 52                 // owned states per warp = 64 - 2*KST
#define NPER 267               // ceil(1599/6); 267*6 = 1602 (tail frozen by t<il)
#define PAIRS 208              // state pairs covered (max pair idx 207)
#define THREADS 512            // 16 warps: 8 per example, 2 examples per CTA
#define LOG2E 1.4426950408889634f
#define LN2   0.6931471805599453f
#define NEG2  (-1.0e30f * 1.4426950408889634f)

// smem: rowbuf[2][RINGR][CC] floats + shA[2 halves][2 bufs][PAIRS] float2
#define OFF_SHA (2 * RINGR * CC)
#define SMEM_BYTES (OFF_SHA * 4 + 2 * 2 * PAIRS * 8)   // 131072 + 6656

__device__ float g_per_ex[NN];
__device__ unsigned int g_count;

__device__ __forceinline__ float ex2f(float x) {
    float y; asm("ex2.approx.ftz.f32 %0, %1;" : "=f"(y) : "f"(x)); return y;
}
__device__ __forceinline__ float lg2f(float x) {
    float y; asm("lg2.approx.ftz.f32 %0, %1;" : "=f"(y) : "f"(x)); return y;
}
__device__ __forceinline__ void cp_async8(void* smem_dst, const void* gmem_src) {
    unsigned s = (unsigned)__cvta_generic_to_shared(smem_dst);
    asm volatile("cp.async.ca.shared.global [%0], [%1], 8;" :: "r"(s), "l"(gmem_src));
}
__device__ __forceinline__ void cp_commit() { asm volatile("cp.async.commit_group;"); }
template<int N>
__device__ __forceinline__ void cp_wait() { asm volatile("cp.async.wait_group %0;" :: "n"(N)); }

__global__ void __launch_bounds__(THREADS, 1)
ctc_kernel(const float* __restrict__ lp,       // (T, N, C)
           const int*   __restrict__ targets,  // (N, S)
           const int*   __restrict__ input_lens,
           const int*   __restrict__ target_lens,
           float*       __restrict__ out)
{
    extern __shared__ float smem[];
    const int tid  = threadIdx.x;
    const int half = tid >> 8;          // which example of this CTA
    const int lt   = tid & 255;         // local tid within half (256 threads)
    const int lw   = (tid >> 5) & 7;    // local warp within half (0..7)
    const int lane = tid & 31;
    const int n    = (blockIdx.x << 1) + half;

    float*  rowbuf = smem + (size_t)half * RINGR * CC;
    float2* shA    = (float2*)(smem + OFF_SHA) + half * (2 * PAIRS);

    // thread owns state pair (sB even/blank, sB+1 odd/label); lanes 0..5 = halo
    const int  sB    = SPW * lw + 2 * (lane - HALO);
    const bool owner = (lane >= HALO);
    const int  pB    = sB >> 1;          // pair index (valid when sB >= 0)

    const size_t NC = (size_t)NN * CC;
    const float* __restrict__ base = lp + (size_t)n * CC;
    const int tl = target_lens[n];
    const int il = input_lens[n];

    // per-pair invariants
    int  myExt = 0;
    bool allow = false;
    if (sB >= 0 && sB < 400) {
        const int idx = sB >> 1;
        myExt = targets[n * SS + idx];
        if (sB >= 2) allow = (myExt != targets[n * SS + idx - 1]);
    }

    // alpha_0 (log2 domain)
    float aE = NEG2, aO = NEG2;
    if (sB == 0) {
        aE = base[0] * LOG2E;
        if (tl >= 1) aO = base[myExt] * LOG2E;
    }
    if (owner) shA[PAIRS + pB] = make_float2(aE, aO);   // buffer 1 (read at p=0)

    // prologue: rows for periods 0..2 (rows 1..18)
#pragma unroll
    for (int q = 0; q < 3; ++q) {
#pragma unroll
        for (int k = 1; k <= KST; ++k) {
            const int r = KST * q + k;
            cp_async8(&rowbuf[(r & (RINGR - 1)) * CC + 2 * lt],
                      base + (size_t)r * NC + 2 * lt);
        }
        cp_commit();
    }

    // main loop: 6 trellis steps per barrier period
    for (int p = 0; p < NPER; ++p) {
        cp_wait<2>();            // this period's 6 rows have landed
        __syncthreads();         // rows + previous period's shA visible

        // halo refresh from previous period's buffer
        if (!owner && sB >= 0) {
            const float2 v = shA[(((p & 1) ^ 1) * PAIRS) + pB];
            aE = v.x; aO = v.y;
        }

        const int t0 = KST * p;
        float eB[KST], eO[KST];
#pragma unroll
        for (int k = 0; k < KST; ++k) {
            const float* row = rowbuf + (size_t)((t0 + 1 + k) & (RINGR - 1)) * CC;
            eB[k] = row[0]     * LOG2E;   // blank emit (broadcast LDS)
            eO[k] = row[myExt] * LOG2E;   // label emit (gather)
        }

#pragma unroll
        for (int k = 0; k < KST; ++k) {
            const int t = t0 + 1 + k;
            const float nbO = __shfl_up_sync(0xffffffffu, aO, 1);  // alpha(sB-1)
            // q = LSE2(aE, nbO): even-state core (blank never allows skip)
            const float mq = fmaxf(aE, nbO);
            const float dq = fminf(aE, nbO) - mq;
            const float q  = mq + lg2f(1.0f + ex2f(dq));
            const float nvE = q + eB[k];
            // odd state: LSE3(aO, aE, allow?nbO) == LSE2(aO, allow ? q : aE)
            const float qp = allow ? q : aE;
            const float mo = fmaxf(aO, qp);
            const float dd = fminf(aO, qp) - mo;
            const float nvO = mo + lg2f(1.0f + ex2f(dd)) + eO[k];
            const bool act = (t < il);    // also freezes tail steps t > 1600
            aE = act ? nvE : aE;
            aO = act ? nvO : aO;
        }

        // prefetch rows for period p+3 (in-flight slots <= 24 < 32: no aliasing)
        {
            const int r0 = KST * (p + 3);
#pragma unroll
            for (int k = 1; k <= KST; ++k) {
                const int r = r0 + k;
                if (r < TT)
                    cp_async8(&rowbuf[(r & (RINGR - 1)) * CC + 2 * lt],
                              base + (size_t)r * NC + 2 * lt);
            }
            cp_commit();   // empty groups keep accounting aligned
        }

        // publish this period's alpha for next period's halo
        if (owner) shA[((p & 1) * PAIRS) + pB] = make_float2(aE, aO);
    }
    // last period (p=266) published into buffer 0

    __syncthreads();

    // readout + fused mean reduction (one thread per example)
    if (lt == 0) {
        const float al = shA[tl].x;                       // state 2*tl (final blank)
        const float ap = (tl > 0) ? shA[tl - 1].y : NEG2; // state 2*tl - 1
        const float mm = fmaxf(al, ap);
        const float lo = fminf(al, ap);
        float loss = -LN2 * (mm + lg2f(1.0f + ex2f(lo - mm)));
        if (!(loss < 1e29f)) loss = 0.0f;                 // zero_infinity (+NaN kill)
        const float norm = sqrtf(fmaxf((float)tl, 1.0f)); // ALPHA = 0.5
        ((volatile float*)g_per_ex)[n] = loss / norm;
        __threadfence();
        const unsigned old = atomicAdd(&g_count, 1u);     // one ticket per example
        if ((old % NN) == (NN - 1)) {                     // last of this replay reduces
            __threadfence();
            float acc = 0.0f;
#pragma unroll
            for (int i = 0; i < NN; ++i) acc += ((volatile float*)g_per_ex)[i];
            out[0] = acc / (float)NN;
        }
    }
}

extern "C" void kernel_launch(void* const* d_in, const int* in_sizes, int n_in,
                              void* d_out, int out_size)
{
    const float* log_probs   = (const float*)d_in[0];
    const int*   targets     = (const int*)d_in[1];
    const int*   input_lens  = (const int*)d_in[2];
    const int*   target_lens = (const int*)d_in[3];
    float* out = (float*)d_out;

    cudaFuncSetAttribute(ctc_kernel,
                         cudaFuncAttributeMaxDynamicSharedMemorySize, SMEM_BYTES);
    ctc_kernel<<<NN / 2, THREADS, SMEM_BYTES>>>(log_probs, targets,
                                                input_lens, target_lens, out);
}

// round 9
// speedup vs baseline: 1.6555x; 1.2257x over previous
#include <cuda_runtime.h>
#include <math.h>

// Problem constants (fixed by dataset)
#define TT 1600
#define NN 32
#define CC 512
#define SS 200
#define RINGR 32               // row ring slots per example (power of 2)
#define KST 6                  // trellis steps per barrier period
#define HALO 6                 // halo pair-lanes per warp
#define SPW 52                 // owned states per warp (26 pairs)
#define NPER 267               // covers t=1..1602 (tail frozen by act)
#define PAIRS 208
#define THREADS 512            // 16 warps: 8 per example, 2 examples per CTA
#define LOG2E 1.4426950408889634f
#define ESENT (-(1 << 28))     // "empty pair" exponent sentinel

// ---- dynamic smem layout ----
#define OFF_SHA   (2 * RINGR * CC)                  // float index of shA
#define OFF_SHE   (OFF_SHA * 4 + 2 * 2 * PAIRS * 8) // byte offset of shE
#define SMEM_BYTES (OFF_SHE + 2 * 2 * PAIRS * 4)    // ~137.8 KB

__device__ float g_per_ex[NN];
__device__ unsigned int g_count;

__device__ __forceinline__ float ex2f(float x) {
    float y; asm("ex2.approx.ftz.f32 %0, %1;" : "=f"(y) : "f"(x)); return y;
}
// exact 2^k for k <= 0 (0 below normal range); k=0 -> 1
__device__ __forceinline__ float exp2neg(int k) {
    return (k <= -127) ? 0.0f : __uint_as_float((unsigned)(127 + k) << 23);
}
__device__ __forceinline__ void cp_async16(void* smem_dst, const void* gmem_src) {
    unsigned s = (unsigned)__cvta_generic_to_shared(smem_dst);
    asm volatile("cp.async.cg.shared.global [%0], [%1], 16;" :: "r"(s), "l"(gmem_src));
}
__device__ __forceinline__ void cp_commit() { asm volatile("cp.async.commit_group;"); }
template<int N>
__device__ __forceinline__ void cp_wait() { asm volatile("cp.async.wait_group %0;" :: "n"(N)); }

__global__ void __launch_bounds__(THREADS, 1)
ctc_kernel(const float* __restrict__ lp,       // (T, N, C)
           const int*   __restrict__ targets,  // (N, S)
           const int*   __restrict__ input_lens,
           const int*   __restrict__ target_lens,
           float*       __restrict__ out)
{
    extern __shared__ float smem[];
    const int tid  = threadIdx.x;
    const int half = tid >> 8;
    const int lt   = tid & 255;
    const int lw   = (tid >> 5) & 7;
    const int lane = tid & 31;
    const int n    = (blockIdx.x << 1) + half;

    float*  rowbuf = smem + (size_t)half * RINGR * CC;
    float2* shA    = (float2*)(smem + OFF_SHA) + half * (2 * PAIRS);    // [2][PAIRS]
    int*    shE    = (int*)((char*)smem + OFF_SHE) + half * (2 * PAIRS);// [2][PAIRS]

    const int  sB    = SPW * lw + 2 * (lane - HALO);   // even state of my pair
    const bool owner = (lane >= HALO);
    const int  pB    = sB >> 1;                        // valid when sB >= 0

    const size_t NC = (size_t)NN * CC;
    const float* __restrict__ base = lp + (size_t)n * CC;
    const int tl = target_lens[n];
    const int il = input_lens[n];

    // per-pair invariants
    int   myExt  = 0;
    bool  allow  = false;
    if (sB >= 0) {
        const int idx = min(sB >> 1, SS - 1);
        myExt = targets[n * SS + idx];
        if (sB >= 2 && sB < 400)
            allow = (myExt != targets[n * SS + idx - 1]);
    }
    const float gE = (sB >= 0 && sB <= 400) ? 1.0f : 0.0f;  // state sB valid
    const float gO = (sB >= 0 && sB <  400) ? 1.0f : 0.0f;  // state sB+1 valid

    // ---- alpha_0 in linear domain with per-thread exponent ----
    float aE = 0.0f, aO = 0.0f;
    int   E  = ESENT;
    if (sB == 0) {
        aE = ex2f(base[0] * LOG2E);
        if (tl >= 1) aO = ex2f(base[myExt] * LOG2E);
        E = 0;
    }
    if (owner) { shA[PAIRS + pB] = make_float2(aE, aO); shE[PAIRS + pB] = E; }

    // ---- prologue: rows for periods 0..2 (rows 1..18), 16B cp.async ----
    const int g   = lt >> 7;          // row group (0/1) within half
    const int cid = lt & 127;         // 16B chunk within row
#pragma unroll
    for (int q = 0; q < 3; ++q) {
#pragma unroll
        for (int j = 0; j < 3; ++j) {
            const int r = KST * q + 1 + 3 * g + j;
            cp_async16(&rowbuf[(r & (RINGR - 1)) * CC + cid * 4],
                       base + (size_t)r * NC + cid * 4);
        }
        cp_commit();
    }

    // ================== main loop ==================
    for (int p = 0; p < NPER; ++p) {
        cp_wait<2>();
        __syncthreads();      // rows of period p + prev-period shA/shE visible

        // ---- halo refresh (value + exponent) ----
        const int prevb = (p & 1) ^ 1;
        if (lane < HALO && sB >= 0) {
            const float2 v = shA[prevb * PAIRS + pB];
            aE = v.x; aO = v.y;
            E  = shE[prevb * PAIRS + pB];
        }

        // ---- per-warp inclusive max-scan of E -> M (monotone in lane) ----
        int M = E;
#pragma unroll
        for (int o = 1; o < 32; o <<= 1) {
            const int v = __shfl_up_sync(0xffffffffu, M, o);
            if (lane >= o) M = max(M, v);
        }
        const float fSelf = exp2neg(E - M);     // <= 1 (E <= M)
        aE *= fSelf; aO *= fSelf; E = M;
        const int   Mnb  = __shfl_up_sync(0xffffffffu, M, 1);
        const float fNb  = exp2neg(Mnb - M);    // <= 1; lane 0 garbage-tolerant
        const float fNbA = allow ? fNb : 0.0f;

        const int t0 = KST * p;
        // gather + convert emits to linear (only MUFU work; off critical chain)
        float eB[KST], eO[KST];
#pragma unroll
        for (int k = 0; k < KST; ++k) {
            const float* row = rowbuf + (size_t)((t0 + 1 + k) & (RINGR - 1)) * CC;
            eB[k] = gE * ex2f(row[0]     * LOG2E);
            eO[k] = gO * ex2f(row[myExt] * LOG2E);
        }

        // ---- 6 trellis steps: pure FMA-pipe + 1 shfl ----
#pragma unroll
        for (int k = 0; k < KST; ++k) {
            const int t = t0 + 1 + k;
            const float nbO = __shfl_up_sync(0xffffffffu, aO, 1);  // alpha(sB-1)
            const float sE  = fmaf(nbO, fNb,  aE);
            const float sO  = fmaf(nbO, fNbA, aE + aO);
            const float nE  = sE * eB[k];
            const float nO  = sO * eO[k];
            const bool act = (t < il);
            aE = act ? nE : aE;
            aO = act ? nO : aO;
        }

        // ---- prefetch rows for period p+3 ----
        {
            const int r0 = KST * (p + 3) + 1 + 3 * g;
#pragma unroll
            for (int j = 0; j < 3; ++j) {
                const int r = r0 + j;
                if (r < TT)
                    cp_async16(&rowbuf[(r & (RINGR - 1)) * CC + cid * 4],
                               base + (size_t)r * NC + cid * 4);
            }
            cp_commit();
        }

        // ---- per-thread exact power-of-2 renorm ----
        const float m = fmaxf(aE, aO);
        if (m > 0.0f) {
            const int e = (int)((__float_as_uint(m) >> 23) & 255) - 127;
            const float sc = __uint_as_float((unsigned)(127 - e) << 23);  // 2^{-e}
            aE *= sc; aO *= sc; E += e;
        } else {
            E = ESENT;
        }

        // publish for next period's halo
        if (owner) {
            shA[(p & 1) * PAIRS + pB] = make_float2(aE, aO);
            shE[(p & 1) * PAIRS + pB] = E;
        }
    }
    // final alphas in buffer (NPER-1)&1 = 0

    __syncthreads();

    // ---- readout (double precision, once) + fused mean reduction ----
    if (lt == 0) {
        const float2 vL = shA[tl];          // pair tl: state 2*tl (final blank)
        const int    EL = shE[tl];
        float aPv = 0.0f; int EP = 0;
        if (tl > 0) { aPv = shA[tl - 1].y; EP = shE[tl - 1]; }  // state 2*tl-1
        const double l1 = (vL.x > 0.0f) ? (double)EL + log2((double)vL.x) : -1e30;
        const double l2 = (aPv  > 0.0f) ? (double)EP + log2((double)aPv) : -1e30;
        const double mm = fmax(l1, l2);
        const double lo = fmin(l1, l2);
        double loss = -0.6931471805599453 * (mm + log2(1.0 + exp2(lo - mm)));
        if (!(loss < 1e29)) loss = 0.0;                    // zero_infinity (+NaN kill)
        const float norm = sqrtf(fmaxf((float)tl, 1.0f));  // ALPHA = 0.5
        ((volatile float*)g_per_ex)[n] = (float)loss / norm;
        __threadfence();
        const unsigned old = atomicAdd(&g_count, 1u);
        if ((old % NN) == (NN - 1)) {                      // last example of replay
            __threadfence();
            float acc = 0.0f;
#pragma unroll
            for (int i = 0; i < NN; ++i) acc += ((volatile float*)g_per_ex)[i];
            out[0] = acc / (float)NN;
        }
    }
}

extern "C" void kernel_launch(void* const* d_in, const int* in_sizes, int n_in,
                              void* d_out, int out_size)
{
    const float* log_probs   = (const float*)d_in[0];
    const int*   targets     = (const int*)d_in[1];
    const int*   input_lens  = (const int*)d_in[2];
    const int*   target_lens = (const int*)d_in[3];
    float* out = (float*)d_out;

    cudaFuncSetAttribute(ctc_kernel,
                         cudaFuncAttributeMaxDynamicSharedMemorySize, SMEM_BYTES);
    ctc_kernel<<<NN / 2, THREADS, SMEM_BYTES>>>(log_probs, targets,
                                                input_lens, target_lens, out);
}

// round 10
// speedup vs baseline: 2.3434x; 1.4155x over previous
#include <cuda_runtime.h>
#include <math.h>

// Problem constants (fixed by dataset)
#define TT 1600
#define NN 32
#define CC 512
#define SS 200
#define RINGR 32               // row ring slots (power of 2)
#define KST 6                  // trellis steps per barrier period
#define HALO 6                 // halo pair-lanes per warp
#define SPW 52                 // owned states per warp (26 pairs)
#define NPER 267               // covers t=1..1602 (tail frozen by act)
#define PAIRS 208
#define THREADS 256            // 8 warps, one example per CTA
#define LOG2E 1.4426950408889634f
#define ESENT (-(1 << 28))     // "empty pair" exponent sentinel

// ---- dynamic smem layout ----
#define OFF_SHA   (RINGR * CC)                     // float index of shA
#define OFF_SHE   (OFF_SHA * 4 + 2 * PAIRS * 8)    // byte offset of shE
#define SMEM_BYTES (OFF_SHE + 2 * PAIRS * 4)       // ~70.2 KB

__device__ float g_per_ex[NN];
__device__ unsigned int g_count;

__device__ __forceinline__ float ex2f(float x) {
    float y; asm("ex2.approx.ftz.f32 %0, %1;" : "=f"(y) : "f"(x)); return y;
}
// exact 2^k for k <= 0 (0 below normal range); k=0 -> 1
__device__ __forceinline__ float exp2neg(int k) {
    return (k <= -127) ? 0.0f : __uint_as_float((unsigned)(127 + k) << 23);
}
__device__ __forceinline__ void cp_async16(void* smem_dst, const void* gmem_src) {
    unsigned s = (unsigned)__cvta_generic_to_shared(smem_dst);
    asm volatile("cp.async.cg.shared.global [%0], [%1], 16;" :: "r"(s), "l"(gmem_src));
}
__device__ __forceinline__ void cp_commit() { asm volatile("cp.async.commit_group;"); }
template<int N>
__device__ __forceinline__ void cp_wait() { asm volatile("cp.async.wait_group %0;" :: "n"(N)); }

__global__ void __launch_bounds__(THREADS, 1)
ctc_kernel(const float* __restrict__ lp,       // (T, N, C)
           const int*   __restrict__ targets,  // (N, S)
           const int*   __restrict__ input_lens,
           const int*   __restrict__ target_lens,
           float*       __restrict__ out)
{
    extern __shared__ float smem[];
    const int tid  = threadIdx.x;
    const int lw   = tid >> 5;          // warp 0..7
    const int lane = tid & 31;
    const int n    = blockIdx.x;

    float*  rowbuf = smem;                                   // [RINGR][CC]
    float2* shA    = (float2*)(smem + OFF_SHA);              // [2][PAIRS]
    int*    shE    = (int*)((char*)smem + OFF_SHE);          // [2][PAIRS]

    const int  sB    = SPW * lw + 2 * (lane - HALO);   // even state of my pair
    const bool owner = (lane >= HALO);
    const int  pB    = sB >> 1;                        // valid when sB >= 0

    const size_t NC = (size_t)NN * CC;
    const float* __restrict__ base = lp + (size_t)n * CC;
    const int tl = target_lens[n];
    const int il = input_lens[n];

    // per-pair invariants
    int  myExt = 0;
    bool allow = false;
    if (sB >= 0) {
        const int idx = min(sB >> 1, SS - 1);
        myExt = targets[n * SS + idx];
        if (sB >= 2 && sB < 400)
            allow = (myExt != targets[n * SS + idx - 1]);
    }
    const float gE = (sB >= 0 && sB <= 400) ? 1.0f : 0.0f;  // state sB valid
    const float gO = (sB >= 0 && sB <  400) ? 1.0f : 0.0f;  // state sB+1 valid

    // ---- alpha_0 in linear domain with per-thread exponent ----
    float aE = 0.0f, aO = 0.0f;
    int   E  = ESENT;
    if (sB == 0) {
        aE = ex2f(base[0] * LOG2E);
        if (tl >= 1) aO = ex2f(base[myExt] * LOG2E);
        E = 0;
    }
    if (owner) { shA[PAIRS + pB] = make_float2(aE, aO); shE[PAIRS + pB] = E; }

    // ---- prologue: rows for periods 0..2 (rows 1..18), 16B cp.async ----
    const int g   = tid >> 7;          // row group (0/1)
    const int cid = tid & 127;         // 16B chunk within row
#pragma unroll
    for (int q = 0; q < 3; ++q) {
#pragma unroll
        for (int j = 0; j < 3; ++j) {
            const int r = KST * q + 1 + 3 * g + j;
            cp_async16(&rowbuf[(r & (RINGR - 1)) * CC + cid * 4],
                       base + (size_t)r * NC + cid * 4);
        }
        cp_commit();
    }

    // ================== main loop ==================
    for (int p = 0; p < NPER; ++p) {
        cp_wait<2>();
        __syncthreads();      // rows of period p + prev-period shA/shE visible

        // ---- halo refresh (value + exponent) ----
        const int prevb = (p & 1) ^ 1;
        if (lane < HALO && sB >= 0) {
            const float2 v = shA[prevb * PAIRS + pB];
            aE = v.x; aO = v.y;
            E  = shE[prevb * PAIRS + pB];
        }

        // ---- per-warp inclusive max-scan of E -> M (monotone in lane) ----
        int M = E;
#pragma unroll
        for (int o = 1; o < 32; o <<= 1) {
            const int v = __shfl_up_sync(0xffffffffu, M, o);
            if (lane >= o) M = max(M, v);
        }
        const float fSelf = exp2neg(E - M);     // <= 1 (E <= M)
        aE *= fSelf; aO *= fSelf; E = M;
        const int   Mnb  = __shfl_up_sync(0xffffffffu, M, 1);
        const float fNb  = exp2neg(Mnb - M);    // <= 1; lane 0 garbage-tolerant
        const float fNbA = allow ? fNb : 0.0f;

        const int t0 = KST * p;
        // gather + convert emits to linear (only MUFU work; off critical chain)
        float eB[KST], eO[KST];
#pragma unroll
        for (int k = 0; k < KST; ++k) {
            const float* row = rowbuf + (size_t)((t0 + 1 + k) & (RINGR - 1)) * CC;
            eB[k] = gE * ex2f(row[0]     * LOG2E);
            eO[k] = gO * ex2f(row[myExt] * LOG2E);
        }

        // ---- 6 trellis steps: pure FMA-pipe + 1 shfl ----
#pragma unroll
        for (int k = 0; k < KST; ++k) {
            const int t = t0 + 1 + k;
            const float nbO = __shfl_up_sync(0xffffffffu, aO, 1);  // alpha(sB-1)
            const float sE  = fmaf(nbO, fNb,  aE);
            const float sO  = fmaf(nbO, fNbA, aE + aO);
            const float nE  = sE * eB[k];
            const float nO  = sO * eO[k];
            const bool act = (t < il);
            aE = act ? nE : aE;
            aO = act ? nO : aO;
        }

        // ---- prefetch rows for period p+3 ----
        {
            const int r0 = KST * (p + 3) + 1 + 3 * g;
#pragma unroll
            for (int j = 0; j < 3; ++j) {
                const int r = r0 + j;
                if (r < TT)
                    cp_async16(&rowbuf[(r & (RINGR - 1)) * CC + cid * 4],
                               base + (size_t)r * NC + cid * 4);
            }
            cp_commit();
        }

        // ---- per-thread exact power-of-2 renorm ----
        const float m = fmaxf(aE, aO);
        if (m > 0.0f) {
            const int e = (int)((__float_as_uint(m) >> 23) & 255) - 127;
            const float sc = __uint_as_float((unsigned)(127 - e) << 23);  // 2^{-e}
            aE *= sc; aO *= sc; E += e;
        } else {
            E = ESENT;
        }

        // publish for next period's halo
        if (owner) {
            shA[(p & 1) * PAIRS + pB] = make_float2(aE, aO);
            shE[(p & 1) * PAIRS + pB] = E;
        }
    }
    // final alphas in buffer (NPER-1)&1 = 0

    __syncthreads();

    // ---- readout (double precision, once) + fused mean reduction ----
    if (tid == 0) {
        const float2 vL = shA[tl];          // pair tl: state 2*tl (final blank)
        const int    EL = shE[tl];
        float aPv = 0.0f; int EP = 0;
        if (tl > 0) { aPv = shA[tl - 1].y; EP = shE[tl - 1]; }  // state 2*tl-1
        const double l1 = (vL.x > 0.0f) ? (double)EL + log2((double)vL.x) : -1e30;
        const double l2 = (aPv  > 0.0f) ? (double)EP + log2((double)aPv) : -1e30;
        const double mm = fmax(l1, l2);
        const double lo = fmin(l1, l2);
        double loss = -0.6931471805599453 * (mm + log2(1.0 + exp2(lo - mm)));
        if (!(loss < 1e29)) loss = 0.0;                    // zero_infinity (+NaN kill)
        const float norm = sqrtf(fmaxf((float)tl, 1.0f));  // ALPHA = 0.5
        ((volatile float*)g_per_ex)[n] = (float)loss / norm;
        __threadfence();
        const unsigned old = atomicAdd(&g_count, 1u);
        if ((old % NN) == (NN - 1)) {                      // last example of replay
            __threadfence();
            float acc = 0.0f;
#pragma unroll
            for (int i = 0; i < NN; ++i) acc += ((volatile float*)g_per_ex)[i];
            out[0] = acc / (float)NN;
        }
    }
}

extern "C" void kernel_launch(void* const* d_in, const int* in_sizes, int n_in,
                              void* d_out, int out_size)
{
    const float* log_probs   = (const float*)d_in[0];
    const int*   targets     = (const int*)d_in[1];
    const int*   input_lens  = (const int*)d_in[2];
    const int*   target_lens = (const int*)d_in[3];
    float* out = (float*)d_out;

    cudaFuncSetAttribute(ctc_kernel,
                         cudaFuncAttributeMaxDynamicSharedMemorySize, SMEM_BYTES);
    ctc_kernel<<<NN, THREADS, SMEM_BYTES>>>(log_probs, targets,
                                            input_lens, target_lens, out);
}